// round 2
// baseline (speedup 1.0000x reference)
#include <cuda_runtime.h>
#include <cuda_bf16.h>

// Problem constants: B=8, C=64, H=W=128, G=2, D=32, K=9, OS=2.0
#define PB 16384
#define NB 8
#define NROWS (NB * PB)

typedef unsigned long long ull;

__device__ float g_value[NB * PB * 64];   // (b,p,64)
__device__ float g_om[NB * PB * 54];      // (b,p,54)

// ---- packed f32x2 helpers -------------------------------------------------
__device__ __forceinline__ ull pack2(float lo, float hi) {
    ull r; asm("mov.b64 %0, {%1,%2};" : "=l"(r) : "f"(lo), "f"(hi)); return r;
}
__device__ __forceinline__ void ffma2(ull& d, ull a, ull b) {
    asm("fma.rn.f32x2 %0, %1, %2, %0;" : "+l"(d) : "l"(a), "l"(b));
}
__device__ __forceinline__ float2 unpack2(ull v) {
    float2 r; asm("mov.b64 {%0,%1}, %2;" : "=f"(r.x), "=f"(r.y) : "l"(v)); return r;
}

// ---------------------------------------------------------------------------
// K1: value projection. Tile 128 rows x 64 j, 256 thr, thread = 8 rows x 4 j.
// A stored transposed in smem (At[c][r]) so row-pairs are packed f32x2 operands.
// smem: 32768 + 16384 = 49152 B (exactly 48KB).
// ---------------------------------------------------------------------------
__global__ void __launch_bounds__(256) k1_valproj(const float* __restrict__ x,
                                                  const float* __restrict__ vp_w,
                                                  const float* __restrict__ vp_b) {
    __shared__ float At[64 * 128];   // At[c*128 + r]
    __shared__ float Wt[64 * 64];    // Wt[c*64 + j]
    int t = threadIdx.x;
    for (int i = t; i < 4096; i += 256) Wt[(i & 63) * 64 + (i >> 6)] = vp_w[i];

    size_t row0 = (size_t)blockIdx.x * 128;
    const float4* xv = (const float4*)(x + row0 * 64);
    for (int i = t; i < 2048; i += 256) {
        int r = i >> 4, c4 = (i & 15) * 4;
        float4 v = xv[i];
        At[(c4 + 0) * 128 + r] = v.x;
        At[(c4 + 1) * 128 + r] = v.y;
        At[(c4 + 2) * 128 + r] = v.z;
        At[(c4 + 3) * 128 + r] = v.w;
    }
    __syncthreads();

    int j0 = (t & 15) * 4;
    int r0 = (t >> 4) * 8;
    ull acc[4][4];
#pragma unroll
    for (int i = 0; i < 4; i++)
#pragma unroll
        for (int j = 0; j < 4; j++) acc[i][j] = 0ull;

    const float* ap = At + r0;
    const float* wp = Wt + j0;
#pragma unroll 8
    for (int c = 0; c < 64; c++) {
        ulonglong2 aA = *(const ulonglong2*)(ap + c * 128);      // rows r0..r0+3
        ulonglong2 aB = *(const ulonglong2*)(ap + c * 128 + 4);  // rows r0+4..r0+7
        float4 b = *(const float4*)(wp + c * 64);
        ull b0 = pack2(b.x, b.x), b1 = pack2(b.y, b.y);
        ull b2 = pack2(b.z, b.z), b3 = pack2(b.w, b.w);
        ffma2(acc[0][0], aA.x, b0); ffma2(acc[0][1], aA.x, b1);
        ffma2(acc[0][2], aA.x, b2); ffma2(acc[0][3], aA.x, b3);
        ffma2(acc[1][0], aA.y, b0); ffma2(acc[1][1], aA.y, b1);
        ffma2(acc[1][2], aA.y, b2); ffma2(acc[1][3], aA.y, b3);
        ffma2(acc[2][0], aB.x, b0); ffma2(acc[2][1], aB.x, b1);
        ffma2(acc[2][2], aB.x, b2); ffma2(acc[2][3], aB.x, b3);
        ffma2(acc[3][0], aB.y, b0); ffma2(acc[3][1], aB.y, b1);
        ffma2(acc[3][2], aB.y, b2); ffma2(acc[3][3], aB.y, b3);
    }
    float4 bias = __ldg((const float4*)(vp_b + j0));
#pragma unroll
    for (int pr = 0; pr < 4; pr++) {
        float2 v0 = unpack2(acc[pr][0]);
        float2 v1 = unpack2(acc[pr][1]);
        float2 v2 = unpack2(acc[pr][2]);
        float2 v3 = unpack2(acc[pr][3]);
        size_t rA = row0 + r0 + 2 * pr;
        *(float4*)&g_value[rA * 64 + j0] =
            make_float4(v0.x + bias.x, v1.x + bias.y, v2.x + bias.z, v3.x + bias.w);
        *(float4*)&g_value[(rA + 1) * 64 + j0] =
            make_float4(v0.y + bias.x, v1.y + bias.y, v2.y + bias.z, v3.y + bias.w);
    }
}

// ---------------------------------------------------------------------------
// K2: depthwise 3x3 conv (sliding window) + om GEMM (64->54, padded to 64).
// Block = 64 consecutive pixels of one image row. 256 threads.
// ---------------------------------------------------------------------------
__global__ void __launch_bounds__(256) k2_dwom(const float* __restrict__ x,
                                               const float* __restrict__ dw_w,
                                               const float* __restrict__ dw_b,
                                               const float* __restrict__ om_w,
                                               const float* __restrict__ om_b) {
    __shared__ float dwt[64 * 66];   // dwt[c*66 + px]  (transposed conv output)
    __shared__ float Wom[64 * 64];   // Wom[c*64 + j], cols 54..63 zero
    __shared__ float ob[64];
    int t = threadIdx.x;
    for (int i = t; i < 4096; i += 256) {
        int c = i >> 6, j = i & 63;
        Wom[c * 64 + j] = (j < 54) ? om_w[j * 64 + c] : 0.f;
    }
    if (t < 64) ob[t] = (t < 54) ? om_b[t] : 0.f;

    int bb = blockIdx.x >> 8;
    int p0 = (blockIdx.x & 255) * 64;
    int h = p0 >> 7;
    int w0 = p0 & 127;
    const float* xb = x + (size_t)bb * (PB * 64);

    // Phase A: conv. thread = (channel c, pixel group pg of 16).
    {
        int c = t & 63;
        int pg = t >> 6;
        float wk[9];
#pragma unroll
        for (int k = 0; k < 9; k++) wk[k] = dw_w[c * 9 + k];
        float bias = dw_b[c];
        int wstart = w0 + pg * 16;
        const float* xc = xb + c;
        float v[3][3];
#pragma unroll
        for (int ky = 0; ky < 3; ky++) {
            int yy = h + ky - 1;
            bool yok = (unsigned)yy < 128u;
            int xm1 = wstart - 1;
            v[ky][1] = (yok && (unsigned)xm1 < 128u)
                           ? __ldg(xc + ((size_t)((yy << 7) + xm1) << 6)) : 0.f;
            v[ky][2] = yok ? __ldg(xc + ((size_t)((yy << 7) + wstart) << 6)) : 0.f;
        }
        for (int i = 0; i < 16; i++) {
            int w = wstart + i;
            int xp1 = w + 1;
#pragma unroll
            for (int ky = 0; ky < 3; ky++) {
                int yy = h + ky - 1;
                v[ky][0] = v[ky][1];
                v[ky][1] = v[ky][2];
                v[ky][2] = ((unsigned)yy < 128u && (unsigned)xp1 < 128u)
                               ? __ldg(xc + ((size_t)((yy << 7) + xp1) << 6)) : 0.f;
            }
            float acc = bias;
#pragma unroll
            for (int ky = 0; ky < 3; ky++)
#pragma unroll
                for (int kx = 0; kx < 3; kx++)
                    acc = fmaf(v[ky][kx], wk[ky * 3 + kx], acc);
            dwt[c * 66 + pg * 16 + i] = acc;
        }
    }
    __syncthreads();

    // Phase B: om GEMM. thread = 4 px (2 pairs) x 4 j.
    {
        int px0 = (t >> 4) * 4;
        int j0 = (t & 15) * 4;
        ull acc[2][4];
#pragma unroll
        for (int i = 0; i < 2; i++)
#pragma unroll
            for (int j = 0; j < 4; j++) acc[i][j] = 0ull;
        const float* ap = dwt + px0;
        const float* wp = Wom + j0;
#pragma unroll 8
        for (int c = 0; c < 64; c++) {
            ull a0 = *(const ull*)(ap + c * 66);
            ull a1 = *(const ull*)(ap + c * 66 + 2);
            float4 b = *(const float4*)(wp + c * 64);
            ull b0 = pack2(b.x, b.x), b1 = pack2(b.y, b.y);
            ull b2 = pack2(b.z, b.z), b3 = pack2(b.w, b.w);
            ffma2(acc[0][0], a0, b0); ffma2(acc[0][1], a0, b1);
            ffma2(acc[0][2], a0, b2); ffma2(acc[0][3], a0, b3);
            ffma2(acc[1][0], a1, b0); ffma2(acc[1][1], a1, b1);
            ffma2(acc[1][2], a1, b2); ffma2(acc[1][3], a1, b3);
        }
        if (j0 < 54) {
#pragma unroll
            for (int pr = 0; pr < 2; pr++) {
                float2 v0 = unpack2(acc[pr][0]);
                float2 v1 = unpack2(acc[pr][1]);
                float2 v2 = unpack2(acc[pr][2]);
                float2 v3 = unpack2(acc[pr][3]);
                float rlo[4] = {v0.x, v1.x, v2.x, v3.x};
                float rhi[4] = {v0.y, v1.y, v2.y, v3.y};
                size_t baseL = ((size_t)bb * PB + p0 + px0 + 2 * pr) * 54;
                size_t baseH = baseL + 54;
#pragma unroll
                for (int jj = 0; jj < 4; jj++) {
                    int j = j0 + jj;
                    if (j < 54) {
                        g_om[baseL + j] = rlo[jj] + ob[j];
                        g_om[baseH + j] = rhi[jj] + ob[j];
                    }
                }
            }
        }
    }
}

// ---------------------------------------------------------------------------
// K3: DCN bilinear gather (f32x2) + op GEMM (f32x2) + in-register channel
// fold + BN + ReLU. Block = 64 local pixels: p0..p0+31 and p0+8192..+8223.
// ---------------------------------------------------------------------------
__global__ void __launch_bounds__(256) k3_dcn(const float* __restrict__ op_w,
                                              const float* __restrict__ op_b,
                                              const float* __restrict__ bn_g,
                                              const float* __restrict__ bn_b,
                                              const float* __restrict__ bn_m,
                                              const float* __restrict__ bn_v,
                                              float* __restrict__ out) {
    __shared__ float cst[64 * 66];   // cst[c*66 + pl]  (core output transposed)
    __shared__ float Wop[64 * 64];   // Wop[c*64 + j]
    __shared__ float oms[64][54];
    __shared__ float opb[64];
    int t = threadIdx.x;
    for (int i = t; i < 4096; i += 256) Wop[(i & 63) * 64 + (i >> 6)] = op_w[i];
    if (t < 64) opb[t] = op_b[t];

    int bb = blockIdx.x >> 8;
    int p0 = (blockIdx.x & 255) * 32;   // in [0, 8192)

    for (int i = t; i < 64 * 54; i += 256) {
        int pl = i / 54;
        int j = i - pl * 54;
        int p = p0 + ((pl < 32) ? pl : (pl - 32 + 8192));
        oms[pl][j] = g_om[((size_t)bb * PB + p) * 54 + j];
    }
    __syncthreads();

    // DCN gather: 16 lanes per pixel, 4 passes over 64 local pixels.
    {
        int sub = t & 15;
        int g = sub >> 3;
        int d0 = (sub & 7) * 4;
        int plh = t >> 4;
        int cb = g * 32 + d0;
        const float* vb = g_value + (size_t)bb * (PB * 64) + cb;
#pragma unroll
        for (int pass = 0; pass < 4; pass++) {
            int pl = plh + pass * 16;
            int p = p0 + ((pl < 32) ? pl : (pl - 32 + 8192));
            int h = p >> 7;
            int w = p & 127;
            const float* omp = &oms[pl][g * 27];
            ull ac0 = 0ull, ac1 = 0ull;
#pragma unroll
            for (int k = 0; k < 9; k++) {
                float ox = omp[2 * k], oy = omp[2 * k + 1], m = omp[18 + k];
                float ix = (float)w + ((float)(k % 3) - 1.0f + ox) * 2.0f;
                float iy = (float)h + ((float)(k / 3) - 1.0f + oy) * 2.0f;
                float xf = floorf(ix), yf = floorf(iy);
                float tx = ix - xf, ty = iy - yf;
                int x0 = (int)xf, y0 = (int)yf;
                float wx0 = 1.f - tx, wy0 = 1.f - ty;
#pragma unroll
                for (int cr = 0; cr < 4; cr++) {
                    int dy = cr >> 1, dx = cr & 1;
                    int xc = x0 + dx, yc = y0 + dy;
                    if ((unsigned)xc < 128u && (unsigned)yc < 128u) {
                        float wgt = (dy ? ty : wy0) * (dx ? tx : wx0) * m;
                        ulonglong2 v = *(const ulonglong2*)(vb + ((size_t)((yc << 7) + xc) << 6));
                        ull wd = pack2(wgt, wgt);
                        ffma2(ac0, v.x, wd);
                        ffma2(ac1, v.y, wd);
                    }
                }
            }
            float2 r0 = unpack2(ac0);
            float2 r1 = unpack2(ac1);
            cst[(cb + 0) * 66 + pl] = r0.x;
            cst[(cb + 1) * 66 + pl] = r0.y;
            cst[(cb + 2) * 66 + pl] = r1.x;
            cst[(cb + 3) * 66 + pl] = r1.y;
        }
    }
    __syncthreads();

    // op GEMM + fold + BN + ReLU. thread = px {2g,2g+1,2g+32,2g+33} x 4 j.
    {
        int px0 = (t >> 4) * 2;          // 0..30 even
        int j0 = (t & 15) * 4;
        ull acc[2][4];
#pragma unroll
        for (int i = 0; i < 2; i++)
#pragma unroll
            for (int j = 0; j < 4; j++) acc[i][j] = 0ull;
        const float* ap = cst + px0;
        const float* wp = Wop + j0;
#pragma unroll 8
        for (int c = 0; c < 64; c++) {
            ull aL = *(const ull*)(ap + c * 66);        // pl px0, px0+1
            ull aH = *(const ull*)(ap + c * 66 + 32);   // pl px0+32, px0+33
            float4 b = *(const float4*)(wp + c * 64);
            ull b0 = pack2(b.x, b.x), b1 = pack2(b.y, b.y);
            ull b2 = pack2(b.z, b.z), b3 = pack2(b.w, b.w);
            ffma2(acc[0][0], aL, b0); ffma2(acc[0][1], aL, b1);
            ffma2(acc[0][2], aL, b2); ffma2(acc[0][3], aL, b3);
            ffma2(acc[1][0], aH, b0); ffma2(acc[1][1], aH, b1);
            ffma2(acc[1][2], aH, b2); ffma2(acc[1][3], aH, b3);
        }

        int cz = p0 >> 8;
        float sA = __ldg(bn_g + cz) * rsqrtf(__ldg(bn_v + cz) + 1e-5f);
        float sB = fmaf(-sA, __ldg(bn_m + cz), __ldg(bn_b + cz));

        float ze[4], zo[4];
#pragma unroll
        for (int jj = 0; jj < 4; jj++) {
            float2 lo = unpack2(acc[0][jj]);   // (px0, px0+1)
            float2 hi = unpack2(acc[1][jj]);   // (px0+32, px0+33)
            float bj = opb[j0 + jj];
            ze[jj] = fmaf(0.5f * (lo.x + hi.x) + bj, sA, sB);
            zo[jj] = fmaf(0.5f * (lo.y + hi.y) + bj, sA, sB);
        }
        int pE = p0 + px0;                 // even -> q=0
        int hh = (pE >> 1) & 127;
        size_t base = (((size_t)bb * 32 + cz) * 128 + hh) * 128;
        *(float4*)&out[base + j0] =
            make_float4(fmaxf(ze[0], 0.f), fmaxf(ze[1], 0.f),
                        fmaxf(ze[2], 0.f), fmaxf(ze[3], 0.f));
        *(float4*)&out[base + 64 + j0] =
            make_float4(fmaxf(zo[0], 0.f), fmaxf(zo[1], 0.f),
                        fmaxf(zo[2], 0.f), fmaxf(zo[3], 0.f));
    }
}

// ---------------------------------------------------------------------------
extern "C" void kernel_launch(void* const* d_in, const int* in_sizes, int n_in,
                              void* d_out, int out_size) {
    const float* x    = (const float*)d_in[0];
    const float* vp_w = (const float*)d_in[1];
    const float* vp_b = (const float*)d_in[2];
    const float* dw_w = (const float*)d_in[3];
    const float* dw_b = (const float*)d_in[4];
    const float* om_w = (const float*)d_in[5];
    const float* om_b = (const float*)d_in[6];
    const float* op_w = (const float*)d_in[7];
    const float* op_b = (const float*)d_in[8];
    const float* bn_g = (const float*)d_in[9];
    const float* bn_b = (const float*)d_in[10];
    const float* bn_m = (const float*)d_in[11];
    const float* bn_v = (const float*)d_in[12];
    float* out = (float*)d_out;

    k1_valproj<<<NROWS / 128, 256>>>(x, vp_w, vp_b);
    k2_dwom<<<NB * (PB / 64), 256>>>(x, dw_w, dw_b, om_w, om_b);
    k3_dcn<<<NB * 256, 256>>>(op_w, op_b, bn_g, bn_b, bn_m, bn_v, out);
}